// round 4
// baseline (speedup 1.0000x reference)
#include <cuda_runtime.h>

// Problem: B=1, L=768, D_SINGLE=384, D_PAIR=128
//   left  = s @ W[:384] + bias   (768x128)   [bias folded into left]
//   right = s @ W[384:]          (768x128)
//   out[i,j,f] = left[i,f] + right[j,f]      -> 768*768*128 fp32 = 302 MB
//
// Single fused kernel: blocks 0..127 produce left/right, everyone then
// consumes after an intra-kernel acquire/release handoff.
//
// Inputs (metadata order): s (768*384 f32), z (UNUSED), W (768*128 f32), bias (128 f32)

#define L_DIM 768
#define DS 384
#define DP 128
#define TI 6                         // rows per proj block -> 768/6 = 128 proj blocks
#define NPROJ (L_DIM / TI)           // 128
#define NCHUNK (L_DIM / 128)         // 6 j-chunks
#define GRID (L_DIM * NCHUNK)        // 4608 blocks

// scratch (no cudaMalloc allowed)
__device__ float g_left[L_DIM * DP];     // includes bias
__device__ float g_right[L_DIM * DP];
__device__ unsigned g_done;              // proj blocks finished (reset at kernel end)
__device__ unsigned g_exit;              // blocks finished (for the reset)

__global__ __launch_bounds__(256) void fused_kernel(
    const float* __restrict__ s,     // [768, 384]
    const float* __restrict__ W,     // [768, 128]
    const float* __restrict__ bias,  // [128]
    float* __restrict__ out)         // [768, 768, 128]
{
    __shared__ float s_sh[TI][DS];
    const int bid = blockIdx.x;
    const int tid = threadIdx.x;

    // ---------------- producer phase: blocks 0..127 ----------------
    if (bid < NPROJ) {
        const int i0 = bid * TI;
        for (int idx = tid; idx < TI * DS; idx += 256) {
            int r = idx / DS, c = idx % DS;
            s_sh[r][c] = s[(size_t)(i0 + r) * DS + c];
        }
        __syncthreads();

        const int f    = tid & 127;
        const int half = tid >> 7;                  // 0 = left, 1 = right
        const float* Wcol = W + (size_t)(half ? DS : 0) * DP + f;

        float acc[TI];
#pragma unroll
        for (int ii = 0; ii < TI; ii++) acc[ii] = 0.f;

        const float4 (*s4)[DS / 4] = reinterpret_cast<const float4 (*)[DS / 4]>(s_sh);

#pragma unroll 4
        for (int k4 = 0; k4 < DS / 4; k4++) {
            const int kb = k4 * 4;
            float w0 = Wcol[(size_t)(kb + 0) * DP];
            float w1 = Wcol[(size_t)(kb + 1) * DP];
            float w2 = Wcol[(size_t)(kb + 2) * DP];
            float w3 = Wcol[(size_t)(kb + 3) * DP];
#pragma unroll
            for (int ii = 0; ii < TI; ii++) {
                float4 sv = s4[ii][k4];             // one LDS.128, warp-broadcast
                acc[ii] = fmaf(sv.x, w0, acc[ii]);
                acc[ii] = fmaf(sv.y, w1, acc[ii]);
                acc[ii] = fmaf(sv.z, w2, acc[ii]);
                acc[ii] = fmaf(sv.w, w3, acc[ii]);
            }
        }

        if (half == 0) {
            const float b = bias[f];
#pragma unroll
            for (int ii = 0; ii < TI; ii++)
                g_left[(size_t)(i0 + ii) * DP + f] = acc[ii] + b;
        } else {
#pragma unroll
            for (int ii = 0; ii < TI; ii++)
                g_right[(size_t)(i0 + ii) * DP + f] = acc[ii];
        }

        __syncthreads();                 // all threads' stores issued
        if (tid == 0) {
            __threadfence();             // make block's stores gpu-visible
            atomicAdd(&g_done, 1u);      // publish
        }
    }

    // ---------------- handoff: wait for all 128 producers ----------------
    if (tid == 0) {
        unsigned v;
        do {
            asm volatile("ld.acquire.gpu.global.u32 %0, [%1];"
                         : "=r"(v) : "l"(&g_done));
            if (v >= NPROJ) break;
            __nanosleep(200);
        } while (true);
    }
    __syncthreads();                     // broadcast the acquire to the block

    // ---------------- consumer phase: everyone ----------------
    {
        const int i  = bid / NCHUNK;
        const int j0 = (bid % NCHUNK) * 128;
        const int f4 = tid & 31;
        const int jl = tid >> 5;

        const float4* left4  = reinterpret_cast<const float4*>(g_left);
        const float4* right4 = reinterpret_cast<const float4*>(g_right);
        float4* out4 = reinterpret_cast<float4*>(out);

        const float4 lv = left4[(size_t)i * 32 + f4];   // includes bias
        const size_t orow = ((size_t)i * L_DIM + j0) * 32 + f4;

#pragma unroll 4
        for (int jj = jl; jj < 128; jj += 8) {
            float4 rv = __ldg(right4 + (size_t)(j0 + jj) * 32 + f4);
            float4 o;
            o.x = lv.x + rv.x;
            o.y = lv.y + rv.y;
            o.z = lv.z + rv.z;
            o.w = lv.w + rv.w;
            __stcs(out4 + orow + (size_t)jj * 32, o);   // streaming store
        }
    }

    // ---------------- epilogue: last block resets the counters ----------------
    __syncthreads();
    if (tid == 0) {
        __threadfence();
        unsigned e = atomicAdd(&g_exit, 1u);
        if (e == GRID - 1) {             // I'm the last block to finish
            atomicExch(&g_done, 0u);
            atomicExch(&g_exit, 0u);
        }
    }
}

// ---------------------------------------------------------------------------
extern "C" void kernel_launch(void* const* d_in, const int* in_sizes, int n_in,
                              void* d_out, int out_size)
{
    const float* s    = (const float*)d_in[0];
    // d_in[1] = z : intentionally unused (reference never reads it)
    const float* W    = (const float*)d_in[2];
    const float* bias = (const float*)d_in[3];
    float* out = (float*)d_out;

    fused_kernel<<<GRID, 256>>>(s, W, bias, out);
}

// round 5
// speedup vs baseline: 1.0364x; 1.0364x over previous
#include <cuda_runtime.h>

// Problem: B=1, L=768, D_SINGLE=384, D_PAIR=128
//   left  = s @ W[:384] + bias   (768x128)   [bias folded into left]
//   right = s @ W[384:]          (768x128)
//   out[i,j,f] = left[i,f] + right[j,f]      -> 768*768*128 fp32 = 302 MB
//
// Two kernels chained by PDL: proj triggers programmatic completion right
// after its stores; bcast launches early and hardware-waits via
// cudaGridDependencySynchronize() — no inter-kernel launch bubble, no
// software polling storm.
//
// Inputs (metadata order): s (768*384 f32), z (UNUSED), W (768*128 f32), bias (128 f32)

#define L_DIM 768
#define DS 384
#define DP 128
#define TI 6          // rows per proj block -> 768/6 = 128 blocks (single wave)

// scratch (no cudaMalloc allowed)
__device__ float g_left[L_DIM * DP];    // includes bias
__device__ float g_right[L_DIM * DP];

// ---------------------------------------------------------------------------
// Kernel 1: projections. 128 blocks x 256 threads.
// f = tid&127 output column, half = tid>>7 selects left/right.
// s staged in smem, consumed as float4 (warp-broadcast LDS.128).
// W scalar LDG, coalesced across the 128 f-threads (L2-hot).
// ---------------------------------------------------------------------------
__global__ __launch_bounds__(256) void proj_kernel(
    const float* __restrict__ s,     // [768, 384]
    const float* __restrict__ W,     // [768, 128]
    const float* __restrict__ bias)  // [128]
{
    __shared__ float s_sh[TI][DS];
    const int i0  = blockIdx.x * TI;
    const int tid = threadIdx.x;

    for (int idx = tid; idx < TI * DS; idx += 256) {
        int r = idx / DS, c = idx % DS;
        s_sh[r][c] = s[(size_t)(i0 + r) * DS + c];
    }
    __syncthreads();

    const int f    = tid & 127;
    const int half = tid >> 7;                    // 0 = left, 1 = right
    const float* Wcol = W + (size_t)(half ? DS : 0) * DP + f;

    float acc[TI];
#pragma unroll
    for (int ii = 0; ii < TI; ii++) acc[ii] = 0.f;

    const float4 (*s4)[DS / 4] = reinterpret_cast<const float4 (*)[DS / 4]>(s_sh);

#pragma unroll 4
    for (int k4 = 0; k4 < DS / 4; k4++) {
        const int kb = k4 * 4;
        float w0 = Wcol[(size_t)(kb + 0) * DP];
        float w1 = Wcol[(size_t)(kb + 1) * DP];
        float w2 = Wcol[(size_t)(kb + 2) * DP];
        float w3 = Wcol[(size_t)(kb + 3) * DP];
#pragma unroll
        for (int ii = 0; ii < TI; ii++) {
            float4 sv = s4[ii][k4];               // one LDS.128, warp-broadcast
            acc[ii] = fmaf(sv.x, w0, acc[ii]);
            acc[ii] = fmaf(sv.y, w1, acc[ii]);
            acc[ii] = fmaf(sv.z, w2, acc[ii]);
            acc[ii] = fmaf(sv.w, w3, acc[ii]);
        }
    }

    if (half == 0) {
        const float b = bias[f];
#pragma unroll
        for (int ii = 0; ii < TI; ii++)
            g_left[(size_t)(i0 + ii) * DP + f] = acc[ii] + b;
    } else {
#pragma unroll
        for (int ii = 0; ii < TI; ii++)
            g_right[(size_t)(i0 + ii) * DP + f] = acc[ii];
    }

    // PDL: this block's contribution is done — make stores visible, then
    // signal. Secondary launches once ALL blocks have triggered (or exited).
    __syncthreads();
    __threadfence();
    cudaTriggerProgrammaticLaunchCompletion();
}

// ---------------------------------------------------------------------------
// Kernel 2: broadcast-add. out[i,j,f] = left[i,f] + right[j,f].
// Launched with programmatic stream serialization: blocks come up while proj
// still runs, hardware-wait on the grid dependency, then stream stores.
// ---------------------------------------------------------------------------
__global__ __launch_bounds__(256) void bcast_kernel(float* __restrict__ out)
{
    const int i   = blockIdx.y;
    const int j0  = blockIdx.x * 128;
    const int tid = threadIdx.x;
    const int f4  = tid & 31;
    const int jl  = tid >> 5;

    cudaGridDependencySynchronize();   // wait for proj's triggered stores

    const float4* left4  = reinterpret_cast<const float4*>(g_left);
    const float4* right4 = reinterpret_cast<const float4*>(g_right);
    float4* out4 = reinterpret_cast<float4*>(out);

    const float4 lv = left4[(size_t)i * 32 + f4];       // includes bias
    const size_t orow = ((size_t)i * L_DIM + j0) * 32 + f4;

#pragma unroll 4
    for (int jj = jl; jj < 128; jj += 8) {
        float4 rv = __ldg(right4 + (size_t)(j0 + jj) * 32 + f4);
        float4 o;
        o.x = lv.x + rv.x;
        o.y = lv.y + rv.y;
        o.z = lv.z + rv.z;
        o.w = lv.w + rv.w;
        __stcs(out4 + orow + (size_t)jj * 32, o);       // streaming store
    }
}

// ---------------------------------------------------------------------------
extern "C" void kernel_launch(void* const* d_in, const int* in_sizes, int n_in,
                              void* d_out, int out_size)
{
    const float* s    = (const float*)d_in[0];
    // d_in[1] = z : intentionally unused (reference never reads it)
    const float* W    = (const float*)d_in[2];
    const float* bias = (const float*)d_in[3];
    float* out = (float*)d_out;

    proj_kernel<<<L_DIM / TI, 256>>>(s, W, bias);

    // Secondary with PDL attribute: may launch while proj is still running;
    // correctness enforced by cudaGridDependencySynchronize() in-kernel.
    cudaLaunchConfig_t cfg = {};
    cfg.gridDim  = dim3(L_DIM / 128, L_DIM);   // (6, 768)
    cfg.blockDim = dim3(256, 1, 1);
    cfg.dynamicSmemBytes = 0;
    cfg.stream = 0;                            // legacy default stream (captured)

    cudaLaunchAttribute attr;
    attr.id = cudaLaunchAttributeProgrammaticStreamSerialization;
    attr.val.programmaticStreamSerializationAllowed = 1;
    cfg.attrs = &attr;
    cfg.numAttrs = 1;

    cudaLaunchKernelEx(&cfg, bcast_kernel, out);
}